// round 10
// baseline (speedup 1.0000x reference)
#include <cuda_runtime.h>
#include <math.h>

#define Bn 64
#define Tn 800
#define Un 64
#define Nn 64
#define Kn 10
#define Hn 512
#define On 121
#define G4H 2048
#define HB (Hn*Bn)      /* 32768 */
#define NB (Nn*Bn)      /* 4096  */
#define NCTA 128

typedef unsigned long long ull;

// Eigen/XLA-CPU pexp clamps its argument at ln(2^-126); replicate so the
// underflow tail ties bit-exactly (argmax -> 0) like the reference.
#define EXP_LO (-87.33654f)

// sW layout offsets (floats)
#define SW1_OFF (579*16)            /* 9264  */
#define SW2_OFF ((579+1091)*16)     /* 26720 */
#define SP_OFF  ((579+1091+1091)*16)/* 44176 */
#define SH_OFF  (SP_OFF + 8192)     /* 52368 */
#define SMEM_FUSED ((SP_OFF + 8192 + 512) * 4)  /* 211520 B */

// ---------------- device scratch (static, no allocations) ----------------
__device__ __align__(16) float g_h0[Tn*HB];          // [t][d][b]
__device__ __align__(16) float g_h1[Tn*HB];
__device__ __align__(16) float g_h2[Tn*HB];
__device__ __align__(16) float g_w [Tn*NB];          // [t][n][b]
__device__ __align__(16) float g_xT[Tn*3*Bn];        // [t][dim][b]
__device__ unsigned g_barc[4];                       // monotone barrier counters

// ---------------- fp32x2 helpers -----------------------------------------
__device__ __forceinline__ void fma2(ull &acc, ull a, ull b) {
    asm("fma.rn.f32x2 %0, %1, %2, %0;" : "+l"(acc) : "l"(a), "l"(b));
}
__device__ __forceinline__ void add2(ull &a, ull b) {
    asm("add.rn.f32x2 %0, %0, %1;" : "+l"(a) : "l"(b));
}
__device__ __forceinline__ ull dup2(float w) {
    ull r; asm("mov.b64 %0, {%1, %1};" : "=l"(r) : "f"(w)); return r;
}
__device__ __forceinline__ void unpack2(ull v, float &lo, float &hi) {
    asm("mov.b64 {%0, %1}, %2;" : "=f"(lo), "=f"(hi) : "l"(v));
}

// 8 cols x 4 batches accumulate
__device__ __forceinline__ void mac8(ull* acc, ulonglong2 in, float4 w0, float4 w1) {
    fma2(acc[0],  in.x, dup2(w0.x)); fma2(acc[1],  in.y, dup2(w0.x));
    fma2(acc[2],  in.x, dup2(w0.y)); fma2(acc[3],  in.y, dup2(w0.y));
    fma2(acc[4],  in.x, dup2(w0.z)); fma2(acc[5],  in.y, dup2(w0.z));
    fma2(acc[6],  in.x, dup2(w0.w)); fma2(acc[7],  in.y, dup2(w0.w));
    fma2(acc[8],  in.x, dup2(w1.x)); fma2(acc[9],  in.y, dup2(w1.x));
    fma2(acc[10], in.x, dup2(w1.y)); fma2(acc[11], in.y, dup2(w1.y));
    fma2(acc[12], in.x, dup2(w1.z)); fma2(acc[13], in.y, dup2(w1.z));
    fma2(acc[14], in.x, dup2(w1.w)); fma2(acc[15], in.y, dup2(w1.w));
}

// 32 distinct rows per warp, 8-deep LDG prefetch.
__device__ __forceinline__ void gemm_rows32(ull* acc, const float* __restrict__ gp,
                                            const float* __restrict__ wp) {
    ulonglong2 ib[8];
    #pragma unroll
    for (int i = 0; i < 8; ++i)
        ib[i] = *reinterpret_cast<const ulonglong2*>(gp + (size_t)i*64);
    #pragma unroll
    for (int c = 0; c < 4; ++c) {
        #pragma unroll
        for (int i = 0; i < 8; ++i) {
            int r = c*8 + i;
            float4 w0 = *reinterpret_cast<const float4*>(wp + r*16);
            float4 w1 = *reinterpret_cast<const float4*>(wp + r*16 + 4);
            ulonglong2 in = ib[i];
            if (c < 3)
                ib[i] = *reinterpret_cast<const ulonglong2*>(gp + (size_t)(r+8)*64);
            mac8(acc, in, w0, w1);
        }
    }
}

__device__ __forceinline__ void gemm_rowsN(ull* acc, const float* __restrict__ gp,
                                           const float* __restrict__ wp, int n) {
    #pragma unroll 4
    for (int r = 0; r < n; ++r) {
        ulonglong2 in = *reinterpret_cast<const ulonglong2*>(gp + (size_t)r*64);
        float4 w0 = *reinterpret_cast<const float4*>(wp + r*16);
        float4 w1 = *reinterpret_cast<const float4*>(wp + r*16 + 4);
        mac8(acc, in, w0, w1);
    }
}

// sP: [slice 8][col 16][b 64]
__device__ __forceinline__ void store_partials8(float* sP, int slice, int ch, int bg,
                                                const ull* acc) {
    float* pp = sP + slice*1024 + (ch*8)*64 + bg*4;
    #pragma unroll
    for (int j = 0; j < 8; ++j)
        *reinterpret_cast<ulonglong2*>(pp + j*64) = make_ulonglong2(acc[2*j], acc[2*j+1]);
}

__device__ __forceinline__ float reduce8(const float* sP, int col, int b) {
    const float* p = sP + col*64 + b;
    float s0 = p[0]      + p[1024];
    float s1 = p[2*1024] + p[3*1024];
    float s2 = p[4*1024] + p[5*1024];
    float s3 = p[6*1024] + p[7*1024];
    return (s0 + s1) + (s2 + s3);
}

// fast gates (~1e-6 rel err)
__device__ __forceinline__ float sigf2(float x) {
    return __fdividef(1.f, 1.f + __expf(-x));
}
__device__ __forceinline__ float tanhf2(float x) {
    return 1.f - __fdividef(2.f, __expf(2.f*x) + 1.f);
}

// two-round partial reduce + LSTM gates + h store (uniform control flow)
__device__ __forceinline__ void reduce_gates_store(
    float* sP, const ull* acc, int tid, int warp, int ch, int bg,
    int uuR, int bR, const float* sbL, float& creg, float* hout, int u0)
{
    if (warp < 8) store_partials8(sP, warp, ch, bg, acc);
    __syncthreads();
    if (warp >= 8) {
        float* pp = sP + (warp-8)*1024 + (ch*8)*64 + bg*4;
        #pragma unroll
        for (int j = 0; j < 8; ++j) {
            ulonglong2 m = *reinterpret_cast<ulonglong2*>(pp + j*64);
            ull x = m.x, y = m.y;
            add2(x, acc[2*j]); add2(y, acc[2*j+1]);
            *reinterpret_cast<ulonglong2*>(pp + j*64) = make_ulonglong2(x, y);
        }
    }
    __syncthreads();
    if (tid < 256) {
        float z[4];
        #pragma unroll
        for (int g = 0; g < 4; ++g)
            z[g] = sbL[uuR*4 + g] + reduce8(sP, uuR*4 + g, bR);
        float c2 = sigf2(z[1])*creg + sigf2(z[0])*tanhf2(z[2]);
        creg = c2;
        hout[(u0+uuR)*64 + bR] = sigf2(z[3])*tanhf2(c2);
    }
    __syncthreads();
}

// ---------------- release/acquire barrier primitives ---------------------
__device__ __forceinline__ void bar_arrive(int slot) {
    asm volatile("red.release.gpu.global.add.u32 [%0], 1;"
                 :: "l"(g_barc + slot) : "memory");
}
__device__ __forceinline__ void bar_wait_ge(int slot, unsigned target) {
    unsigned v;
    do {
        asm volatile("ld.acquire.gpu.global.u32 %0, [%1];"
                     : "=r"(v) : "l"(g_barc + slot) : "memory");
    } while (v < target);
}

// ---------------- init: barrier vars + stroke transpose ------------------
__global__ void k_init(const float* __restrict__ strokes) {
    int i = blockIdx.x * blockDim.x + threadIdx.x;
    int stride = gridDim.x * blockDim.x;
    for (int j = i; j < Tn*3*Bn; j += stride) {
        int t = j / 192, rem = j % 192, dim = rem / 64, b = rem & 63;
        g_xT[j] = strokes[b*(Tn*3) + t*3 + dim];
    }
    if (i < 4) g_barc[i] = 0u;
}

// =========================================================================
// Fused 3-layer pipelined scan + attention.  128 CTAs x 512 thr persistent.
// Tick t: L0 step t, L1 step t-1, L2 step t-2, attention step t.
// Barrier slots: 0 = h0, 1 = w, 2 = h1, 3 = h2 (monotone, 1 arrive/CTA/tick).
// =========================================================================
__global__ void __launch_bounds__(512, 1)
k_fused(const float* __restrict__ trans,
        const float* __restrict__ W0, const float* __restrict__ R0,
        const float* __restrict__ b0, const float* __restrict__ Wd,
        const float* __restrict__ bd,
        const float* __restrict__ W1, const float* __restrict__ R1,
        const float* __restrict__ b1,
        const float* __restrict__ W2, const float* __restrict__ R2,
        const float* __restrict__ b2,
        float* __restrict__ attOut)
{
    extern __shared__ float sm[];
    float* sW = sm;                 // 44176 floats (L0|L1|L2 weights)
    float* sP = sm + SP_OFF;        // 8*1024
    float* sH = sm + SH_OFF;        // 512
    __shared__ float sb[48];
    __shared__ float sbd[30];
    __shared__ float sPart[16*32];
    __shared__ float sy[32];
    __shared__ float skap[10];
    __shared__ float swf[72];

    const int tid  = threadIdx.x;
    const int lane = tid & 31;
    const int warp = tid >> 5;
    const int bg   = lane & 15;
    const int ch   = lane >> 4;
    const int u0   = blockIdx.x * 4;
    const int bR   = tid & 63;
    const int uuR  = tid >> 6;
    const bool isAtt = (blockIdx.x < Bn);

    // ---- stage weights: L0 rows 0..578 (R0 | W0 w-part | W0 x-part)
    for (int idx = tid; idx < 579*16; idx += 512) {
        int r = idx >> 4, c = idx & 15;
        int col = (c & 3) * 512 + u0 + (c >> 2);
        float v;
        if (r < 512)      v = R0[r*G4H + col];
        else if (r < 576) v = W0[(3 + r - 512)*G4H + col];
        else              v = W0[(r - 576)*G4H + col];
        sW[idx] = v;
    }
    // ---- L1 rows 0..1090 (R1 | W1 h | W1 w | W1 x)
    for (int idx = tid; idx < 1091*16; idx += 512) {
        int r = idx >> 4, c = idx & 15;
        int col = (c & 3) * 512 + u0 + (c >> 2);
        float v;
        if (r < 512)       v = R1[r*G4H + col];
        else if (r < 1024) v = W1[(r - 512)*G4H + col];
        else if (r < 1088) v = W1[(512 + r - 1024)*G4H + col];
        else               v = W1[(576 + r - 1088)*G4H + col];
        sW[SW1_OFF + idx] = v;
    }
    // ---- L2 rows 0..1090
    for (int idx = tid; idx < 1091*16; idx += 512) {
        int r = idx >> 4, c = idx & 15;
        int col = (c & 3) * 512 + u0 + (c >> 2);
        float v;
        if (r < 512)       v = R2[r*G4H + col];
        else if (r < 1024) v = W2[(r - 512)*G4H + col];
        else if (r < 1088) v = W2[(512 + r - 1024)*G4H + col];
        else               v = W2[(576 + r - 1088)*G4H + col];
        sW[SW2_OFF + idx] = v;
    }
    if (tid < 16) {
        sb[tid]      = b0[(tid & 3) * 512 + u0 + (tid >> 2)];
        sb[16 + tid] = b1[(tid & 3) * 512 + u0 + (tid >> 2)];
        sb[32 + tid] = b2[(tid & 3) * 512 + u0 + (tid >> 2)];
    }
    if (tid < 30) sbd[tid] = bd[tid];
    if (tid < 10) skap[tid] = 0.f;
    __syncthreads();

    float c0 = 0.f, c1 = 0.f, c2s = 0.f;

    #pragma unroll 1
    for (int t = 0; t <= Tn + 1; ++t) {
        // ================= L0 (step t) =================
        if (t < Tn) {
            ull acc[16];
            #pragma unroll
            for (int i = 0; i < 16; ++i) acc[i] = 0ull;
            if (t > 0)
                gemm_rows32(acc, g_h0 + (size_t)(t-1)*HB + (warp*32)*64 + bg*4,
                            sW + (warp*32)*16 + ch*8);
            if (warp == 15)
                gemm_rowsN(acc, g_xT + (size_t)t*192 + bg*4, sW + 576*16 + ch*8, 3);
            // w[t-1]: S2 >= t rounds
            if (tid == 0) bar_wait_ge(1, (unsigned)t * NCTA);
            __syncthreads();
            if (t > 0)
                gemm_rowsN(acc, g_w + (size_t)(t-1)*NB + (warp*4)*64 + bg*4,
                           sW + (512 + warp*4)*16 + ch*8, 4);
            reduce_gates_store(sP, acc, tid, warp, ch, bg, uuR, bR,
                               sb, c0, g_h0 + (size_t)t*HB, u0);
        } else {
            // still need w rows for L1/L2 below
            if (tid == 0) bar_wait_ge(1, (unsigned)Tn * NCTA);
            __syncthreads();
        }
        if (tid == 0) bar_arrive(0);              // S1: h0[t]

        // ================= L1 (step t-1) =================
        if (t >= 1) {
            // h1[t-2]: S3 >= t rounds (vacuous at t=1)
            if (tid == 0) bar_wait_ge(2, (unsigned)t * NCTA);
            __syncthreads();
        }
        if (t >= 1 && t <= Tn) {
            const int s = t - 1;
            ull acc[16];
            #pragma unroll
            for (int i = 0; i < 16; ++i) acc[i] = 0ull;
            gemm_rows32(acc, g_h0 + (size_t)s*HB + (warp*32)*64 + bg*4,
                        sW + (SW1_OFF) + (512 + warp*32)*16 + ch*8);
            gemm_rowsN(acc, g_w + (size_t)s*NB + (warp*4)*64 + bg*4,
                       sW + (SW1_OFF) + (1024 + warp*4)*16 + ch*8, 4);
            if (warp == 15)
                gemm_rowsN(acc, g_xT + (size_t)s*192 + bg*4,
                           sW + (SW1_OFF) + 1088*16 + ch*8, 3);
            if (s > 0)
                gemm_rows32(acc, g_h1 + (size_t)(s-1)*HB + (warp*32)*64 + bg*4,
                            sW + (SW1_OFF) + (warp*32)*16 + ch*8);
            reduce_gates_store(sP, acc, tid, warp, ch, bg, uuR, bR,
                               sb + 16, c1, g_h1 + (size_t)s*HB, u0);
        }
        if (tid == 0) bar_arrive(2);              // S3: h1[t-1]

        // ================= L2 (step t-2) =================
        if (t >= 3) {
            // h2[t-3]: S4 >= t rounds
            if (tid == 0) bar_wait_ge(3, (unsigned)t * NCTA);
            __syncthreads();
        }
        if (t >= 2) {
            const int s = t - 2;
            ull acc[16];
            #pragma unroll
            for (int i = 0; i < 16; ++i) acc[i] = 0ull;
            gemm_rows32(acc, g_h1 + (size_t)s*HB + (warp*32)*64 + bg*4,
                        sW + (SW2_OFF) + (512 + warp*32)*16 + ch*8);
            gemm_rowsN(acc, g_w + (size_t)s*NB + (warp*4)*64 + bg*4,
                       sW + (SW2_OFF) + (1024 + warp*4)*16 + ch*8, 4);
            if (warp == 15)
                gemm_rowsN(acc, g_xT + (size_t)s*192 + bg*4,
                           sW + (SW2_OFF) + 1088*16 + ch*8, 3);
            if (s > 0)
                gemm_rows32(acc, g_h2 + (size_t)(s-1)*HB + (warp*32)*64 + bg*4,
                            sW + (SW2_OFF) + (warp*32)*16 + ch*8);
            reduce_gates_store(sP, acc, tid, warp, ch, bg, uuR, bR,
                               sb + 32, c2s, g_h2 + (size_t)s*HB, u0);
        }
        if (tid == 0) bar_arrive(3);              // S4: h2[t-2]

        // ================= attention (step t) =================
        if (t < Tn) {
            if (tid == 0) bar_wait_ge(0, (unsigned)(t+1) * NCTA);  // h0[t] complete
            __syncthreads();
            if (isAtt) {
                const int b = blockIdx.x;
                sH[tid] = g_h0[(size_t)t*HB + tid*64 + b];
                __syncthreads();
                int cc = tid & 31, seg = tid >> 5;
                if (cc < 30) {
                    int dbase = seg * 32;
                    float part = 0.f;
                    #pragma unroll 8
                    for (int d = 0; d < 32; ++d)
                        part += sH[dbase + d] * Wd[(dbase + d)*30 + cc];
                    sPart[seg*32 + cc] = part;
                }
                __syncthreads();
                if (warp == 0) {
                    if (lane < 30) {
                        float y = sbd[lane];
                        #pragma unroll
                        for (int s = 0; s < 16; ++s) y += sPart[s*32 + lane];
                        sy[lane] = expf(y);
                    }
                    __syncwarp();
                    if (lane < Kn) skap[lane] += sy[20 + lane];
                    __syncwarp();
                }
                __syncthreads();
                if (tid < Un + 1) {
                    float s = 0.f;
                    #pragma unroll
                    for (int k = 0; k < Kn; ++k) {
                        float dd  = skap[k] - (float)(tid + 1);
                        float arg = -sy[10 + k] * dd * dd;
                        if (arg < EXP_LO) arg = EXP_LO;   // Eigen pexp clamp
                        s += sy[k] * expf(arg);
                    }
                    swf[tid] = s;
                }
                __syncthreads();
                if (tid < Nn) {
                    float acc2 = 0.f;
                    #pragma unroll 8
                    for (int u = 0; u < Un; ++u)
                        acc2 += swf[u] * trans[b*(Un*Nn) + u*Nn + tid];
                    g_w[(size_t)t*NB + tid*64 + b] = acc2;
                } else if (tid == 64) {
                    float best = swf[0]; int bi = 0;
                    #pragma unroll 8
                    for (int u = 1; u < Un + 1; ++u)
                        if (swf[u] > best) { best = swf[u]; bi = u; }
                    attOut[b*Tn + t] = (float)bi;
                }
                __syncthreads();
            }
        }
        if (tid == 0) bar_arrive(1);              // S2: w[t]
    }
}

// =========================================================================
// Output GEMM: out[b][t][o] = [h0,h1,h2][t] @ Wo + bo   (grid = 800 CTAs)
// =========================================================================
__global__ void __launch_bounds__(256)
k_out(const float* __restrict__ Wo, const float* __restrict__ bo,
      float* __restrict__ out)
{
    const int t = blockIdx.x;
    const int tid = threadIdx.x;
    const int c = tid & 127;
    const int bh = tid >> 7;
    if (c >= On) return;

    ull acc[16];
    ull bias2 = dup2(bo[c]);
    #pragma unroll
    for (int i = 0; i < 16; ++i) acc[i] = bias2;

    #pragma unroll
    for (int l = 0; l < 3; ++l) {
        const float* hp = (l == 0 ? g_h0 : l == 1 ? g_h1 : g_h2) + (size_t)t*HB;
        const float* wp = Wo + (l*512)*On + c;
        #pragma unroll 2
        for (int d = 0; d < 512; ++d) {
            ull wv = dup2(wp[d*On]);
            const ulonglong2* h4 = reinterpret_cast<const ulonglong2*>(hp + d*64 + bh*32);
            #pragma unroll
            for (int q = 0; q < 8; ++q) {
                ulonglong2 hv = h4[q];
                fma2(acc[2*q],   hv.x, wv);
                fma2(acc[2*q+1], hv.y, wv);
            }
        }
    }
    #pragma unroll
    for (int i = 0; i < 16; ++i) {
        float lo, hi; unpack2(acc[i], lo, hi);
        int b = bh*32 + 2*i;
        out[(size_t)b     *(Tn*On) + t*On + c] = lo;
        out[(size_t)(b+1) *(Tn*On) + t*On + c] = hi;
    }
}

// =========================================================================
extern "C" void kernel_launch(void* const* d_in, const int* in_sizes, int n_in,
                              void* d_out, int out_size)
{
    const float* strokes = (const float*)d_in[0];
    const float* trans   = (const float*)d_in[1];
    const float* W0      = (const float*)d_in[2];
    const float* R0      = (const float*)d_in[3];
    const float* b0      = (const float*)d_in[4];
    const float* Wd      = (const float*)d_in[5];
    const float* bd      = (const float*)d_in[6];
    const float* W1      = (const float*)d_in[7];
    const float* R1      = (const float*)d_in[8];
    const float* b1      = (const float*)d_in[9];
    const float* W2      = (const float*)d_in[10];
    const float* R2      = (const float*)d_in[11];
    const float* b2      = (const float*)d_in[12];
    const float* Wo      = (const float*)d_in[13];
    const float* bo      = (const float*)d_in[14];

    float* out = (float*)d_out;
    float* att = out + (size_t)Bn * Tn * On;

    cudaFuncSetAttribute(k_fused, cudaFuncAttributeMaxDynamicSharedMemorySize,
                         SMEM_FUSED);

    k_init<<<256, 256>>>(strokes);
    k_fused<<<NCTA, 512, SMEM_FUSED>>>(trans, W0, R0, b0, Wd, bd,
                                       W1, R1, b1, W2, R2, b2, att);
    k_out<<<Tn, 256>>>(Wo, bo, out);
}

// round 11
// speedup vs baseline: 1.1245x; 1.1245x over previous
#include <cuda_runtime.h>
#include <math.h>

#define Bn 64
#define Tn 800
#define Un 64
#define Nn 64
#define Kn 10
#define Hn 512
#define On 121
#define G4H 2048
#define HB (Hn*Bn)      /* 32768 */
#define NB (Nn*Bn)      /* 4096  */
#define NGEMM 128       /* GEMM-role CTAs in scan0 */
#define NATT  16        /* attention-role CTAs in scan0 */
#define NCTA 128        /* scan12f grid */

typedef unsigned long long ull;

// Eigen/XLA-CPU pexp clamps its argument at ln(2^-126); replicate so the
// underflow tail ties bit-exactly (argmax -> 0) like the reference.
#define EXP_LO (-87.33654f)

// ---------------- device scratch (static, no allocations) ----------------
__device__ __align__(16) float g_h0[Tn*HB];          // [t][d][b]
__device__ __align__(16) float g_h1[Tn*HB];
__device__ __align__(16) float g_h2[Tn*HB];
__device__ __align__(16) float g_w [Tn*NB];          // [t][n][b]
__device__ __align__(16) float g_xT[Tn*3*Bn];        // [t][dim][b]
__device__ unsigned g_barc[4];                       // monotone barrier counters

// ---------------- fp32x2 helpers -----------------------------------------
__device__ __forceinline__ void fma2(ull &acc, ull a, ull b) {
    asm("fma.rn.f32x2 %0, %1, %2, %0;" : "+l"(acc) : "l"(a), "l"(b));
}
__device__ __forceinline__ ull dup2(float w) {
    ull r; asm("mov.b64 %0, {%1, %1};" : "=l"(r) : "f"(w)); return r;
}
__device__ __forceinline__ void unpack2(ull v, float &lo, float &hi) {
    asm("mov.b64 {%0, %1}, %2;" : "=f"(lo), "=f"(hi) : "l"(v));
}

// 8 cols x 4 batches accumulate
__device__ __forceinline__ void mac8(ull* acc, ulonglong2 in, float4 w0, float4 w1) {
    fma2(acc[0],  in.x, dup2(w0.x)); fma2(acc[1],  in.y, dup2(w0.x));
    fma2(acc[2],  in.x, dup2(w0.y)); fma2(acc[3],  in.y, dup2(w0.y));
    fma2(acc[4],  in.x, dup2(w0.z)); fma2(acc[5],  in.y, dup2(w0.z));
    fma2(acc[6],  in.x, dup2(w0.w)); fma2(acc[7],  in.y, dup2(w0.w));
    fma2(acc[8],  in.x, dup2(w1.x)); fma2(acc[9],  in.y, dup2(w1.x));
    fma2(acc[10], in.x, dup2(w1.y)); fma2(acc[11], in.y, dup2(w1.y));
    fma2(acc[12], in.x, dup2(w1.z)); fma2(acc[13], in.y, dup2(w1.z));
    fma2(acc[14], in.x, dup2(w1.w)); fma2(acc[15], in.y, dup2(w1.w));
}

// 32 distinct rows per warp, 8-deep LDG prefetch.
__device__ __forceinline__ void gemm_rows32(ull* acc, const float* __restrict__ gp,
                                            const float* __restrict__ wp) {
    ulonglong2 ib[8];
    #pragma unroll
    for (int i = 0; i < 8; ++i)
        ib[i] = *reinterpret_cast<const ulonglong2*>(gp + (size_t)i*64);
    #pragma unroll
    for (int c = 0; c < 4; ++c) {
        #pragma unroll
        for (int i = 0; i < 8; ++i) {
            int r = c*8 + i;
            float4 w0 = *reinterpret_cast<const float4*>(wp + r*16);
            float4 w1 = *reinterpret_cast<const float4*>(wp + r*16 + 4);
            ulonglong2 in = ib[i];
            if (c < 3)
                ib[i] = *reinterpret_cast<const ulonglong2*>(gp + (size_t)(r+8)*64);
            mac8(acc, in, w0, w1);
        }
    }
}

__device__ __forceinline__ void gemm_rowsN(ull* acc, const float* __restrict__ gp,
                                           const float* __restrict__ wp, int n) {
    #pragma unroll 4
    for (int r = 0; r < n; ++r) {
        ulonglong2 in = *reinterpret_cast<const ulonglong2*>(gp + (size_t)r*64);
        float4 w0 = *reinterpret_cast<const float4*>(wp + r*16);
        float4 w1 = *reinterpret_cast<const float4*>(wp + r*16 + 4);
        mac8(acc, in, w0, w1);
    }
}

// sP layout: [slice 16][col 16][b 64]
__device__ __forceinline__ void store_partials(float* sP, int warp, int ch, int bg,
                                               const ull* acc) {
    float* pp = sP + warp*1024 + (ch*8)*64 + bg*4;
    #pragma unroll
    for (int j = 0; j < 8; ++j)
        *reinterpret_cast<ulonglong2*>(pp + j*64) = make_ulonglong2(acc[2*j], acc[2*j+1]);
}

__device__ __forceinline__ float reduce16(const float* sP, int col, int b) {
    const float* p = sP + col*64 + b;
    float s0 = p[0]       + p[1024];
    float s1 = p[2*1024]  + p[3*1024];
    float s2 = p[4*1024]  + p[5*1024];
    float s3 = p[6*1024]  + p[7*1024];
    s0 += p[8*1024]  + p[9*1024];
    s1 += p[10*1024] + p[11*1024];
    s2 += p[12*1024] + p[13*1024];
    s3 += p[14*1024] + p[15*1024];
    return (s0 + s1) + (s2 + s3);
}

// fast gates (~1e-6 rel err)
__device__ __forceinline__ float sigf2(float x) {
    return __fdividef(1.f, 1.f + __expf(-x));
}
__device__ __forceinline__ float tanhf2(float x) {
    return 1.f - __fdividef(2.f, __expf(2.f*x) + 1.f);
}

// ---------------- release/acquire barrier primitives ---------------------
__device__ __forceinline__ void bar_arrive(int slot) {
    asm volatile("red.release.gpu.global.add.u32 [%0], 1;"
                 :: "l"(g_barc + slot) : "memory");
}
__device__ __forceinline__ void bar_wait_ge(int slot, unsigned target) {
    unsigned v;
    do {
        asm volatile("ld.acquire.gpu.global.u32 %0, [%1];"
                     : "=r"(v) : "l"(g_barc + slot) : "memory");
    } while (v < target);
}

// ---------------- init: barrier vars + stroke transpose ------------------
__global__ void k_init(const float* __restrict__ strokes) {
    int i = blockIdx.x * blockDim.x + threadIdx.x;
    int stride = gridDim.x * blockDim.x;
    for (int j = i; j < Tn*3*Bn; j += stride) {
        int t = j / 192, rem = j % 192, dim = rem / 64, b = rem & 63;
        g_xT[j] = strokes[b*(Tn*3) + t*3 + dim];
    }
    if (i < 4) g_barc[i] = 0u;
}

// =========================================================================
// Layer-0 scan, role-split: 144 CTAs x 512 thr persistent.
//   CTA 0..127  : GEMM role (4 units each; never does attention)
//   CTA 128..143: attention role (4 batches each; Wd+trans in SMEM)
// slot0 = "h0[t] ready" (128 arrivals/step), slot1 = "w[t] ready" (16/step).
// After S1(t): GEMM CTAs start h-GEMM(t+1) while att CTAs produce w[t].
// =========================================================================
__global__ void __launch_bounds__(512, 1)
k_scan0(const float* __restrict__ trans,
        const float* __restrict__ W0, const float* __restrict__ R0,
        const float* __restrict__ b0, const float* __restrict__ Wd,
        const float* __restrict__ bd, float* __restrict__ attOut)
{
    extern __shared__ float sm[];
    const int tid  = threadIdx.x;
    const int lane = tid & 31;
    const int warp = tid >> 5;

    if (blockIdx.x < NGEMM) {
        // ================= GEMM role =================
        float* sW = sm;              // 579*16 = 9264
        float* sP = sm + 9264;       // 16384
        __shared__ float sb[16];

        const int bg  = lane & 15;
        const int ch  = lane >> 4;
        const int u0  = blockIdx.x * 4;
        const int bR  = tid & 63;
        const int uuR = tid >> 6;

        for (int idx = tid; idx < 9264; idx += 512) {
            int r = idx >> 4, c = idx & 15;
            int col = (c & 3) * 512 + u0 + (c >> 2);
            float v;
            if (r < 512)      v = R0[r*G4H + col];
            else if (r < 576) v = W0[(3 + r - 512)*G4H + col];
            else              v = W0[(r - 576)*G4H + col];
            sW[idx] = v;
        }
        if (tid < 16) sb[tid] = b0[(tid & 3) * 512 + u0 + (tid >> 2)];
        __syncthreads();

        float creg = 0.f;
        for (int t = 0; t < Tn; ++t) {
            ull acc[16];
            #pragma unroll
            for (int i = 0; i < 16; ++i) acc[i] = 0ull;
            // h rows: h0[t-1] ready (S1 waited at end of prev iteration)
            if (t > 0)
                gemm_rows32(acc, g_h0 + (size_t)(t-1)*HB + (warp*32)*64 + bg*4,
                            sW + (warp*32)*16 + ch*8);
            if (warp == 15)
                gemm_rowsN(acc, g_xT + (size_t)t*192 + bg*4, sW + 576*16 + ch*8, 3);
            // wait S2: w[t-1] ready (16 att arrivals per step)
            if (tid == 0) bar_wait_ge(1, (unsigned)t * NATT);
            __syncthreads();
            if (t > 0)
                gemm_rowsN(acc, g_w + (size_t)(t-1)*NB + (warp*4)*64 + bg*4,
                           sW + (512 + warp*4)*16 + ch*8, 4);

            store_partials(sP, warp, ch, bg, acc);
            __syncthreads();
            if (tid < 256) {
                float z[4];
                #pragma unroll
                for (int g = 0; g < 4; ++g)
                    z[g] = sb[uuR*4 + g] + reduce16(sP, uuR*4 + g, bR);
                float c2 = sigf2(z[1])*creg + sigf2(z[0])*tanhf2(z[2]);
                creg = c2;
                g_h0[(size_t)t*HB + (u0+uuR)*64 + bR] = sigf2(z[3])*tanhf2(c2);
            }
            __syncthreads();
            if (tid == 0) { bar_arrive(0); bar_wait_ge(0, (unsigned)(t+1) * NGEMM); }
            __syncthreads();
        }
    } else {
        // ================= attention role =================
        float* sWd = sm;                    // 512*30 = 15360
        float* sTr = sm + 15360;            // 4*64*64 = 16384
        float* sH  = sm + 15360 + 16384;    // 4*512 = 2048
        __shared__ float sbd[30];
        __shared__ float sPart[4*4*32];
        __shared__ float sy[4*32];
        __shared__ float skap[4*16];
        __shared__ float swf[4*72];

        const int bb = (blockIdx.x - NGEMM) * 4;   // batch base

        for (int idx = tid; idx < 512*30; idx += 512) sWd[idx] = Wd[idx];
        for (int i = 0; i < 32; ++i) {
            int idx = tid + i*512;                  // 4*64*64 = 16384
            int b_ = idx >> 12;
            sTr[idx] = trans[(bb + b_)*(Un*Nn) + (idx & 4095)];
        }
        if (tid < 30) sbd[tid] = bd[tid];
        if (tid < 64) skap[tid] = 0.f;
        __syncthreads();

        for (int t = 0; t < Tn; ++t) {
            // wait S1: h0[t] fully written
            if (tid == 0) bar_wait_ge(0, (unsigned)(t+1) * NGEMM);
            __syncthreads();

            // stage h0[t][:, bb..bb+3]
            #pragma unroll
            for (int i = 0; i < 4; ++i) {
                int idx = tid + i*512;
                int b_ = idx >> 9, d = idx & 511;
                sH[idx] = g_h0[(size_t)t*HB + d*64 + bb + b_];
            }
            __syncthreads();

            // Wd matvec: warp w -> batch w>>2, segment w&3 (128 dims)
            {
                int b_ = warp >> 2, seg = warp & 3;
                if (lane < 30) {
                    const float* hp = sH + b_*512 + seg*128;
                    const float* wp = sWd + (seg*128)*30 + lane;
                    float part = 0.f;
                    #pragma unroll 8
                    for (int d = 0; d < 128; ++d)
                        part += hp[d] * wp[d*30];
                    sPart[(b_*4 + seg)*32 + lane] = part;
                }
            }
            __syncthreads();

            // y -> exp; kappa update (warps 0..3 = batches)
            if (warp < 4) {
                int b_ = warp;
                if (lane < 30) {
                    float y = sbd[lane];
                    y += sPart[(b_*4+0)*32 + lane];
                    y += sPart[(b_*4+1)*32 + lane];
                    y += sPart[(b_*4+2)*32 + lane];
                    y += sPart[(b_*4+3)*32 + lane];
                    sy[b_*32 + lane] = expf(y);
                }
                __syncwarp();
                if (lane < Kn) skap[b_*16 + lane] += sy[b_*32 + 20 + lane];
                __syncwarp();
            }
            __syncthreads();

            // phi: thread (b_ = tid>>7, u = tid&127 < 65)
            {
                int b_ = tid >> 7, u = tid & 127;
                if (u < Un + 1) {
                    float s = 0.f;
                    #pragma unroll
                    for (int k = 0; k < Kn; ++k) {
                        float dd  = skap[b_*16 + k] - (float)(u + 1);
                        float arg = -sy[b_*32 + 10 + k] * dd * dd;
                        if (arg < EXP_LO) arg = EXP_LO;   // Eigen pexp clamp
                        s += sy[b_*32 + k] * expf(arg);
                    }
                    swf[b_*72 + u] = s;
                }
            }
            __syncthreads();

            // w2 (n = 0..63) + argmax (n == 64)
            {
                int b_ = tid >> 7, n = tid & 127;
                if (n < Nn) {
                    const float* wf = swf + b_*72;
                    const float* tp = sTr + b_*4096 + n;
                    float acc2 = 0.f;
                    #pragma unroll 8
                    for (int u = 0; u < Un; ++u)
                        acc2 += wf[u] * tp[u*64];
                    g_w[(size_t)t*NB + n*64 + bb + b_] = acc2;
                } else if (n == 64) {
                    const float* wf = swf + b_*72;
                    float best = wf[0]; int bi = 0;
                    #pragma unroll 8
                    for (int u = 1; u < Un + 1; ++u)
                        if (wf[u] > best) { best = wf[u]; bi = u; }
                    attOut[(bb + b_)*Tn + t] = (float)bi;
                }
            }
            __syncthreads();
            if (tid == 0) bar_arrive(1);   // S2: w[t] done
        }
    }
}

// =========================================================================
// Fused layers 1/2 scan: z = [h_in, w, x]@Wff + h[t-1]@R + b ; LSTM.
// Feedforward GEMM of step t+1 runs between barrier arrive and wait.
// =========================================================================
__global__ void __launch_bounds__(512, 1)
k_scan12f(const float* __restrict__ R, const float* __restrict__ W,
          const float* __restrict__ bias, int sel)
{
    extern __shared__ float sm[];
    float* sW = sm;                  // 1091*16 = 17456
    float* sP = sm + 17456;          // 16384
    __shared__ float sb[16];

    const float* hin = (sel == 1) ? g_h0 : g_h1;
    float* hseq      = (sel == 1) ? g_h1 : g_h2;
    const int slot = sel + 1;        // 2 or 3
    const int tid  = threadIdx.x;
    const int lane = tid & 31;
    const int warp = tid >> 5;
    const int bg   = lane & 15;
    const int ch   = lane >> 4;
    const int u0   = blockIdx.x * 4;
    const int bR   = tid & 63;
    const int uuR  = tid >> 6;

    for (int idx = tid; idx < 1091*16; idx += 512) {
        int r = idx >> 4, c = idx & 15;
        int col = (c & 3) * 512 + u0 + (c >> 2);
        float v;
        if (r < 512)       v = R[r*G4H + col];
        else if (r < 1024) v = W[(r - 512)*G4H + col];
        else if (r < 1088) v = W[(512 + r - 1024)*G4H + col];
        else               v = W[(576 + r - 1088)*G4H + col];
        sW[idx] = v;
    }
    if (tid < 16) sb[tid] = bias[(tid & 3) * 512 + u0 + (tid >> 2)];
    float creg = 0.f;
    __syncthreads();

    ull acc[16];
    #pragma unroll
    for (int i = 0; i < 16; ++i) acc[i] = 0ull;
    gemm_rows32(acc, hin + (size_t)0*HB + (warp*32)*64 + bg*4,
                sW + (512 + warp*32)*16 + ch*8);
    gemm_rowsN(acc, g_w + (size_t)0*NB + (warp*4)*64 + bg*4,
               sW + (1024 + warp*4)*16 + ch*8, 4);
    if (warp == 15)
        gemm_rowsN(acc, g_xT + (size_t)0*192 + bg*4, sW + 1088*16 + ch*8, 3);

    for (int t = 0; t < Tn; ++t) {
        if (t > 0)
            gemm_rows32(acc, hseq + (size_t)(t-1)*HB + (warp*32)*64 + bg*4,
                        sW + (warp*32)*16 + ch*8);

        store_partials(sP, warp, ch, bg, acc);
        __syncthreads();
        if (tid < 256) {
            float z[4];
            #pragma unroll
            for (int g = 0; g < 4; ++g)
                z[g] = sb[uuR*4 + g] + reduce16(sP, uuR*4 + g, bR);
            float c2 = sigf2(z[1])*creg + sigf2(z[0])*tanhf2(z[2]);
            creg = c2;
            hseq[(size_t)t*HB + (u0+uuR)*64 + bR] = sigf2(z[3])*tanhf2(c2);
        }
        __syncthreads();
        if (tid == 0) bar_arrive(slot);

        #pragma unroll
        for (int i = 0; i < 16; ++i) acc[i] = 0ull;
        if (t < Tn - 1) {
            gemm_rows32(acc, hin + (size_t)(t+1)*HB + (warp*32)*64 + bg*4,
                        sW + (512 + warp*32)*16 + ch*8);
            gemm_rowsN(acc, g_w + (size_t)(t+1)*NB + (warp*4)*64 + bg*4,
                       sW + (1024 + warp*4)*16 + ch*8, 4);
            if (warp == 15)
                gemm_rowsN(acc, g_xT + (size_t)(t+1)*192 + bg*4,
                           sW + 1088*16 + ch*8, 3);
        }
        if (tid == 0) bar_wait_ge(slot, (unsigned)(t+1) * NCTA);
        __syncthreads();
    }
}

// =========================================================================
// Output GEMM: out[b][t][o] = [h0,h1,h2][t] @ Wo + bo   (grid = 800 CTAs)
// =========================================================================
__global__ void __launch_bounds__(256)
k_out(const float* __restrict__ Wo, const float* __restrict__ bo,
      float* __restrict__ out)
{
    const int t = blockIdx.x;
    const int tid = threadIdx.x;
    const int c = tid & 127;
    const int bh = tid >> 7;
    if (c >= On) return;

    ull acc[16];
    ull bias2 = dup2(bo[c]);
    #pragma unroll
    for (int i = 0; i < 16; ++i) acc[i] = bias2;

    #pragma unroll
    for (int l = 0; l < 3; ++l) {
        const float* hp = (l == 0 ? g_h0 : l == 1 ? g_h1 : g_h2) + (size_t)t*HB;
        const float* wp = Wo + (l*512)*On + c;
        #pragma unroll 2
        for (int d = 0; d < 512; ++d) {
            ull wv = dup2(wp[d*On]);
            const ulonglong2* h4 = reinterpret_cast<const ulonglong2*>(hp + d*64 + bh*32);
            #pragma unroll
            for (int q = 0; q < 8; ++q) {
                ulonglong2 hv = h4[q];
                fma2(acc[2*q],   hv.x, wv);
                fma2(acc[2*q+1], hv.y, wv);
            }
        }
    }
    #pragma unroll
    for (int i = 0; i < 16; ++i) {
        float lo, hi; unpack2(acc[i], lo, hi);
        int b = bh*32 + 2*i;
        out[(size_t)b     *(Tn*On) + t*On + c] = lo;
        out[(size_t)(b+1) *(Tn*On) + t*On + c] = hi;
    }
}

// =========================================================================
extern "C" void kernel_launch(void* const* d_in, const int* in_sizes, int n_in,
                              void* d_out, int out_size)
{
    const float* strokes = (const float*)d_in[0];
    const float* trans   = (const float*)d_in[1];
    const float* W0      = (const float*)d_in[2];
    const float* R0      = (const float*)d_in[3];
    const float* b0      = (const float*)d_in[4];
    const float* Wd      = (const float*)d_in[5];
    const float* bd      = (const float*)d_in[6];
    const float* W1      = (const float*)d_in[7];
    const float* R1      = (const float*)d_in[8];
    const float* b1      = (const float*)d_in[9];
    const float* W2      = (const float*)d_in[10];
    const float* R2      = (const float*)d_in[11];
    const float* b2      = (const float*)d_in[12];
    const float* Wo      = (const float*)d_in[13];
    const float* bo      = (const float*)d_in[14];

    float* out = (float*)d_out;
    float* att = out + (size_t)Bn * Tn * On;

    const int smem_scan0 = (15360 + 16384 + 2048) * 4;   // att role max: 135168
    const int smem_s12f  = (17456 + 16384) * 4;          // 135360
    cudaFuncSetAttribute(k_scan0,   cudaFuncAttributeMaxDynamicSharedMemorySize, smem_scan0);
    cudaFuncSetAttribute(k_scan12f, cudaFuncAttributeMaxDynamicSharedMemorySize, smem_s12f);

    k_init<<<256, 256>>>(strokes);
    k_scan0<<<NGEMM + NATT, 512, smem_scan0>>>(trans, W0, R0, b0, Wd, bd, att);
    k_scan12f<<<NCTA, 512, smem_s12f>>>(R1, W1, b1, 1);
    k_scan12f<<<NCTA, 512, smem_s12f>>>(R2, W2, b2, 2);
    k_out<<<Tn, 256>>>(Wo, bo, out);
}

// round 12
// speedup vs baseline: 1.2033x; 1.0700x over previous
#include <cuda_runtime.h>
#include <math.h>

#define Bn 64
#define Tn 800
#define Un 64
#define Nn 64
#define Kn 10
#define Hn 512
#define On 121
#define G4H 2048
#define HB (Hn*Bn)      /* 32768 */
#define NB (Nn*Bn)      /* 4096  */
#define NGEMM 128       /* GEMM-role CTAs in fused L0+L1 */
#define NATT  16        /* attention-role CTAs */
#define NCTA 128        /* scan12f grid */

typedef unsigned long long ull;

// Eigen/XLA-CPU pexp clamps its argument at ln(2^-126); replicate so the
// underflow tail ties bit-exactly (argmax -> 0) like the reference.
#define EXP_LO (-87.33654f)

// kernel-A SMEM layout (floats)
#define SW0_OFF 0               /* 579*16  = 9264  */
#define SW1_OFF 9264            /* 1091*16 = 17456 */
#define SPA_OFF (9264+17456)    /* 16384 */
#define SMEM_A ((SPA_OFF + 16384) * 4)   /* 172416 B */

// ---------------- device scratch (static, no allocations) ----------------
__device__ __align__(16) float g_h0[Tn*HB];          // [t][d][b]
__device__ __align__(16) float g_h1[Tn*HB];
__device__ __align__(16) float g_h2[Tn*HB];
__device__ __align__(16) float g_w [Tn*NB];          // [t][n][b]
__device__ __align__(16) float g_xT[Tn*3*Bn];        // [t][dim][b]
__device__ unsigned g_barc[4];                       // monotone barrier counters

// ---------------- fp32x2 helpers -----------------------------------------
__device__ __forceinline__ void fma2(ull &acc, ull a, ull b) {
    asm("fma.rn.f32x2 %0, %1, %2, %0;" : "+l"(acc) : "l"(a), "l"(b));
}
__device__ __forceinline__ ull dup2(float w) {
    ull r; asm("mov.b64 %0, {%1, %1};" : "=l"(r) : "f"(w)); return r;
}
__device__ __forceinline__ void unpack2(ull v, float &lo, float &hi) {
    asm("mov.b64 {%0, %1}, %2;" : "=f"(lo), "=f"(hi) : "l"(v));
}

// 8 cols x 4 batches accumulate
__device__ __forceinline__ void mac8(ull* acc, ulonglong2 in, float4 w0, float4 w1) {
    fma2(acc[0],  in.x, dup2(w0.x)); fma2(acc[1],  in.y, dup2(w0.x));
    fma2(acc[2],  in.x, dup2(w0.y)); fma2(acc[3],  in.y, dup2(w0.y));
    fma2(acc[4],  in.x, dup2(w0.z)); fma2(acc[5],  in.y, dup2(w0.z));
    fma2(acc[6],  in.x, dup2(w0.w)); fma2(acc[7],  in.y, dup2(w0.w));
    fma2(acc[8],  in.x, dup2(w1.x)); fma2(acc[9],  in.y, dup2(w1.x));
    fma2(acc[10], in.x, dup2(w1.y)); fma2(acc[11], in.y, dup2(w1.y));
    fma2(acc[12], in.x, dup2(w1.z)); fma2(acc[13], in.y, dup2(w1.z));
    fma2(acc[14], in.x, dup2(w1.w)); fma2(acc[15], in.y, dup2(w1.w));
}

// 32 distinct rows per warp, 8-deep LDG prefetch.
__device__ __forceinline__ void gemm_rows32(ull* acc, const float* __restrict__ gp,
                                            const float* __restrict__ wp) {
    ulonglong2 ib[8];
    #pragma unroll
    for (int i = 0; i < 8; ++i)
        ib[i] = *reinterpret_cast<const ulonglong2*>(gp + (size_t)i*64);
    #pragma unroll
    for (int c = 0; c < 4; ++c) {
        #pragma unroll
        for (int i = 0; i < 8; ++i) {
            int r = c*8 + i;
            float4 w0 = *reinterpret_cast<const float4*>(wp + r*16);
            float4 w1 = *reinterpret_cast<const float4*>(wp + r*16 + 4);
            ulonglong2 in = ib[i];
            if (c < 3)
                ib[i] = *reinterpret_cast<const ulonglong2*>(gp + (size_t)(r+8)*64);
            mac8(acc, in, w0, w1);
        }
    }
}

__device__ __forceinline__ void gemm_rowsN(ull* acc, const float* __restrict__ gp,
                                           const float* __restrict__ wp, int n) {
    #pragma unroll 4
    for (int r = 0; r < n; ++r) {
        ulonglong2 in = *reinterpret_cast<const ulonglong2*>(gp + (size_t)r*64);
        float4 w0 = *reinterpret_cast<const float4*>(wp + r*16);
        float4 w1 = *reinterpret_cast<const float4*>(wp + r*16 + 4);
        mac8(acc, in, w0, w1);
    }
}

// sP layout: [slice 16][col 16][b 64]
__device__ __forceinline__ void store_partials(float* sP, int warp, int ch, int bg,
                                               const ull* acc) {
    float* pp = sP + warp*1024 + (ch*8)*64 + bg*4;
    #pragma unroll
    for (int j = 0; j < 8; ++j)
        *reinterpret_cast<ulonglong2*>(pp + j*64) = make_ulonglong2(acc[2*j], acc[2*j+1]);
}

__device__ __forceinline__ float reduce16(const float* sP, int col, int b) {
    const float* p = sP + col*64 + b;
    float s0 = p[0]       + p[1024];
    float s1 = p[2*1024]  + p[3*1024];
    float s2 = p[4*1024]  + p[5*1024];
    float s3 = p[6*1024]  + p[7*1024];
    s0 += p[8*1024]  + p[9*1024];
    s1 += p[10*1024] + p[11*1024];
    s2 += p[12*1024] + p[13*1024];
    s3 += p[14*1024] + p[15*1024];
    return (s0 + s1) + (s2 + s3);
}

// fast gates (~1e-6 rel err)
__device__ __forceinline__ float sigf2(float x) {
    return __fdividef(1.f, 1.f + __expf(-x));
}
__device__ __forceinline__ float tanhf2(float x) {
    return 1.f - __fdividef(2.f, __expf(2.f*x) + 1.f);
}

// ---------------- release/acquire barrier primitives ---------------------
__device__ __forceinline__ void bar_arrive(int slot) {
    asm volatile("red.release.gpu.global.add.u32 [%0], 1;"
                 :: "l"(g_barc + slot) : "memory");
}
__device__ __forceinline__ void bar_wait_ge(int slot, unsigned target) {
    unsigned v;
    do {
        asm volatile("ld.acquire.gpu.global.u32 %0, [%1];"
                     : "=r"(v) : "l"(g_barc + slot) : "memory");
    } while (v < target);
}

// ---------------- init: barrier vars + stroke transpose ------------------
__global__ void k_init(const float* __restrict__ strokes) {
    int i = blockIdx.x * blockDim.x + threadIdx.x;
    int stride = gridDim.x * blockDim.x;
    for (int j = i; j < Tn*3*Bn; j += stride) {
        int t = j / 192, rem = j % 192, dim = rem / 64, b = rem & 63;
        g_xT[j] = strokes[b*(Tn*3) + t*3 + dim];
    }
    if (i < 4) g_barc[i] = 0u;
}

// =========================================================================
// Fused L0+L1 scan + attention.  144 CTAs x 512 thr persistent.
//   CTA 0..127  : GEMM role. Tick t: L0 step t, then L1 step t-1.
//   CTA 128..143: attention role (4 batches each; Wd+trans in SMEM).
// Slots: 0 = h0 (128/tick), 1 = w (16/tick), 2 = h1 (128/tick).
// Every chip-wide wait is preceded by posted independent GEMM work.
// =========================================================================
__global__ void __launch_bounds__(512, 1)
k_scan01(const float* __restrict__ trans,
         const float* __restrict__ W0, const float* __restrict__ R0,
         const float* __restrict__ b0, const float* __restrict__ Wd,
         const float* __restrict__ bd,
         const float* __restrict__ W1, const float* __restrict__ R1,
         const float* __restrict__ b1, float* __restrict__ attOut)
{
    extern __shared__ float sm[];
    const int tid  = threadIdx.x;
    const int lane = tid & 31;
    const int warp = tid >> 5;

    if (blockIdx.x < NGEMM) {
        // ================= GEMM role =================
        float* sW0 = sm + SW0_OFF;       // L0: rows 0..511 R0 | 512..575 W0w | 576..578 W0x
        float* sW1 = sm + SW1_OFF;       // L1: 0..511 R1 | 512..1023 W1h | 1024..1087 W1w | 1088..1090 W1x
        float* sP  = sm + SPA_OFF;
        __shared__ float sb[32];

        const int bg  = lane & 15;
        const int ch  = lane >> 4;
        const int u0  = blockIdx.x * 4;
        const int bR  = tid & 63;
        const int uuR = tid >> 6;

        for (int idx = tid; idx < 579*16; idx += 512) {
            int r = idx >> 4, c = idx & 15;
            int col = (c & 3) * 512 + u0 + (c >> 2);
            float v;
            if (r < 512)      v = R0[r*G4H + col];
            else if (r < 576) v = W0[(3 + r - 512)*G4H + col];
            else              v = W0[(r - 576)*G4H + col];
            sW0[idx] = v;
        }
        for (int idx = tid; idx < 1091*16; idx += 512) {
            int r = idx >> 4, c = idx & 15;
            int col = (c & 3) * 512 + u0 + (c >> 2);
            float v;
            if (r < 512)       v = R1[r*G4H + col];
            else if (r < 1024) v = W1[(r - 512)*G4H + col];
            else if (r < 1088) v = W1[(512 + r - 1024)*G4H + col];
            else               v = W1[(576 + r - 1088)*G4H + col];
            sW1[idx] = v;
        }
        if (tid < 16) {
            sb[tid]      = b0[(tid & 3) * 512 + u0 + (tid >> 2)];
            sb[16 + tid] = b1[(tid & 3) * 512 + u0 + (tid >> 2)];
        }
        __syncthreads();

        float c0 = 0.f, c1 = 0.f;
        for (int t = 0; t <= Tn; ++t) {
            // ---------- L0 step t ----------
            if (t < Tn) {
                ull acc[16];
                #pragma unroll
                for (int i = 0; i < 16; ++i) acc[i] = 0ull;
                if (t > 0)
                    gemm_rows32(acc, g_h0 + (size_t)(t-1)*HB + (warp*32)*64 + bg*4,
                                sW0 + (warp*32)*16 + ch*8);
                if (warp == 15)
                    gemm_rowsN(acc, g_xT + (size_t)t*192 + bg*4,
                               sW0 + 576*16 + ch*8, 3);
                // w[t-1] (hidden behind the h-GEMM above)
                if (tid == 0) bar_wait_ge(1, (unsigned)t * NATT);
                __syncthreads();
                if (t > 0)
                    gemm_rowsN(acc, g_w + (size_t)(t-1)*NB + (warp*4)*64 + bg*4,
                               sW0 + (512 + warp*4)*16 + ch*8, 4);
                store_partials(sP, warp, ch, bg, acc);
                __syncthreads();
                if (tid < 256) {
                    float z[4];
                    #pragma unroll
                    for (int g = 0; g < 4; ++g)
                        z[g] = sb[uuR*4 + g] + reduce16(sP, uuR*4 + g, bR);
                    float cn = sigf2(z[1])*c0 + sigf2(z[0])*tanhf2(z[2]);
                    c0 = cn;
                    g_h0[(size_t)t*HB + (u0+uuR)*64 + bR] = sigf2(z[3])*tanhf2(cn);
                }
                __syncthreads();
                if (tid == 0) bar_arrive(0);     // S1: h0[t]
            } else {
                // final tick: still need w[Tn-1] for L1 step Tn-1
                if (tid == 0) bar_wait_ge(1, (unsigned)Tn * NATT);
                __syncthreads();
            }

            // ---------- L1 step t-1 (hides the S1 round) ----------
            if (t >= 1) {
                const int s = t - 1;
                ull acc[16];
                #pragma unroll
                for (int i = 0; i < 16; ++i) acc[i] = 0ull;
                // ff rows: h0[s] (confirmed), w[s] (confirmed), x[s]
                gemm_rows32(acc, g_h0 + (size_t)s*HB + (warp*32)*64 + bg*4,
                            sW1 + (512 + warp*32)*16 + ch*8);
                gemm_rowsN(acc, g_w + (size_t)s*NB + (warp*4)*64 + bg*4,
                           sW1 + (1024 + warp*4)*16 + ch*8, 4);
                if (warp == 15)
                    gemm_rowsN(acc, g_xT + (size_t)s*192 + bg*4,
                               sW1 + 1088*16 + ch*8, 3);
                if (s > 0) {
                    // h1[s-1] (hidden behind the ff rows above)
                    if (tid == 0) bar_wait_ge(2, (unsigned)s * NGEMM);
                    __syncthreads();
                    gemm_rows32(acc, g_h1 + (size_t)(s-1)*HB + (warp*32)*64 + bg*4,
                                sW1 + (warp*32)*16 + ch*8);
                }
                store_partials(sP, warp, ch, bg, acc);
                __syncthreads();
                if (tid < 256) {
                    float z[4];
                    #pragma unroll
                    for (int g = 0; g < 4; ++g)
                        z[g] = sb[16 + uuR*4 + g] + reduce16(sP, uuR*4 + g, bR);
                    float cn = sigf2(z[1])*c1 + sigf2(z[0])*tanhf2(z[2]);
                    c1 = cn;
                    g_h1[(size_t)s*HB + (u0+uuR)*64 + bR] = sigf2(z[3])*tanhf2(cn);
                }
                __syncthreads();
                if (tid == 0) bar_arrive(2);     // S3: h1[s]
            }

            // ---------- S1(t) completion (hidden behind the L1 block) ----------
            if (t < Tn) {
                if (tid == 0) bar_wait_ge(0, (unsigned)(t+1) * NGEMM);
                __syncthreads();
            }
        }
    } else {
        // ================= attention role =================
        float* sWd = sm;                    // 512*30 = 15360
        float* sTr = sm + 15360;            // 4*64*64 = 16384
        float* sH  = sm + 15360 + 16384;    // 4*512 = 2048
        __shared__ float sbd[30];
        __shared__ float sPart[4*4*32];
        __shared__ float sy[4*32];
        __shared__ float skap[4*16];
        __shared__ float swf[4*72];

        const int bb = (blockIdx.x - NGEMM) * 4;   // batch base

        for (int idx = tid; idx < 512*30; idx += 512) sWd[idx] = Wd[idx];
        for (int i = 0; i < 32; ++i) {
            int idx = tid + i*512;
            int b_ = idx >> 12;
            sTr[idx] = trans[(bb + b_)*(Un*Nn) + (idx & 4095)];
        }
        if (tid < 30) sbd[tid] = bd[tid];
        if (tid < 64) skap[tid] = 0.f;
        __syncthreads();

        for (int t = 0; t < Tn; ++t) {
            if (tid == 0) bar_wait_ge(0, (unsigned)(t+1) * NGEMM);
            __syncthreads();

            #pragma unroll
            for (int i = 0; i < 4; ++i) {
                int idx = tid + i*512;
                int b_ = idx >> 9, d = idx & 511;
                sH[idx] = g_h0[(size_t)t*HB + d*64 + bb + b_];
            }
            __syncthreads();

            {
                int b_ = warp >> 2, seg = warp & 3;
                if (lane < 30) {
                    const float* hp = sH + b_*512 + seg*128;
                    const float* wp = sWd + (seg*128)*30 + lane;
                    float part = 0.f;
                    #pragma unroll 8
                    for (int d = 0; d < 128; ++d)
                        part += hp[d] * wp[d*30];
                    sPart[(b_*4 + seg)*32 + lane] = part;
                }
            }
            __syncthreads();

            if (warp < 4) {
                int b_ = warp;
                if (lane < 30) {
                    float y = sbd[lane];
                    y += sPart[(b_*4+0)*32 + lane];
                    y += sPart[(b_*4+1)*32 + lane];
                    y += sPart[(b_*4+2)*32 + lane];
                    y += sPart[(b_*4+3)*32 + lane];
                    sy[b_*32 + lane] = expf(y);
                }
                __syncwarp();
                if (lane < Kn) skap[b_*16 + lane] += sy[b_*32 + 20 + lane];
                __syncwarp();
            }
            __syncthreads();

            {
                int b_ = tid >> 7, u = tid & 127;
                if (u < Un + 1) {
                    float s = 0.f;
                    #pragma unroll
                    for (int k = 0; k < Kn; ++k) {
                        float dd  = skap[b_*16 + k] - (float)(u + 1);
                        float arg = -sy[b_*32 + 10 + k] * dd * dd;
                        if (arg < EXP_LO) arg = EXP_LO;   // Eigen pexp clamp
                        s += sy[b_*32 + k] * expf(arg);
                    }
                    swf[b_*72 + u] = s;
                }
            }
            __syncthreads();

            {
                int b_ = tid >> 7, n = tid & 127;
                if (n < Nn) {
                    const float* wf = swf + b_*72;
                    const float* tp = sTr + b_*4096 + n;
                    float acc2 = 0.f;
                    #pragma unroll 8
                    for (int u = 0; u < Un; ++u)
                        acc2 += wf[u] * tp[u*64];
                    g_w[(size_t)t*NB + n*64 + bb + b_] = acc2;
                } else if (n == 64) {
                    const float* wf = swf + b_*72;
                    float best = wf[0]; int bi = 0;
                    #pragma unroll 8
                    for (int u = 1; u < Un + 1; ++u)
                        if (wf[u] > best) { best = wf[u]; bi = u; }
                    attOut[(bb + b_)*Tn + t] = (float)bi;
                }
            }
            __syncthreads();
            if (tid == 0) bar_arrive(1);   // S2: w[t] done
        }
    }
}

// =========================================================================
// L2 scan: z = [h1, w, x]@W2 + h2[t-1]@R2 + b ; LSTM. (scan12f pattern)
// =========================================================================
__global__ void __launch_bounds__(512, 1)
k_scan2(const float* __restrict__ R, const float* __restrict__ W,
        const float* __restrict__ bias)
{
    extern __shared__ float sm[];
    float* sW = sm;                  // 1091*16 = 17456
    float* sP = sm + 17456;          // 16384
    __shared__ float sb[16];

    const float* hin = g_h1;
    float* hseq      = g_h2;
    const int slot = 3;
    const int tid  = threadIdx.x;
    const int lane = tid & 31;
    const int warp = tid >> 5;
    const int bg   = lane & 15;
    const int ch   = lane >> 4;
    const int u0   = blockIdx.x * 4;
    const int bR   = tid & 63;
    const int uuR  = tid >> 6;

    for (int idx = tid; idx < 1091*16; idx += 512) {
        int r = idx >> 4, c = idx & 15;
        int col = (c & 3) * 512 + u0 + (c >> 2);
        float v;
        if (r < 512)       v = R[r*G4H + col];
        else if (r < 1024) v = W[(r - 512)*G4H + col];
        else if (r < 1088) v = W[(512 + r - 1024)*G4H + col];
        else               v = W[(576 + r - 1088)*G4H + col];
        sW[idx] = v;
    }
    if (tid < 16) sb[tid] = bias[(tid & 3) * 512 + u0 + (tid >> 2)];
    float creg = 0.f;
    __syncthreads();

    ull acc[16];
    #pragma unroll
    for (int i = 0; i < 16; ++i) acc[i] = 0ull;
    gemm_rows32(acc, hin + (size_t)0*HB + (warp*32)*64 + bg*4,
                sW + (512 + warp*32)*16 + ch*8);
    gemm_rowsN(acc, g_w + (size_t)0*NB + (warp*4)*64 + bg*4,
               sW + (1024 + warp*4)*16 + ch*8, 4);
    if (warp == 15)
        gemm_rowsN(acc, g_xT + (size_t)0*192 + bg*4, sW + 1088*16 + ch*8, 3);

    for (int t = 0; t < Tn; ++t) {
        if (t > 0)
            gemm_rows32(acc, hseq + (size_t)(t-1)*HB + (warp*32)*64 + bg*4,
                        sW + (warp*32)*16 + ch*8);

        store_partials(sP, warp, ch, bg, acc);
        __syncthreads();
        if (tid < 256) {
            float z[4];
            #pragma unroll
            for (int g = 0; g < 4; ++g)
                z[g] = sb[uuR*4 + g] + reduce16(sP, uuR*4 + g, bR);
            float c2 = sigf2(z[1])*creg + sigf2(z[0])*tanhf2(z[2]);
            creg = c2;
            hseq[(size_t)t*HB + (u0+uuR)*64 + bR] = sigf2(z[3])*tanhf2(c2);
        }
        __syncthreads();
        if (tid == 0) bar_arrive(slot);

        #pragma unroll
        for (int i = 0; i < 16; ++i) acc[i] = 0ull;
        if (t < Tn - 1) {
            gemm_rows32(acc, hin + (size_t)(t+1)*HB + (warp*32)*64 + bg*4,
                        sW + (512 + warp*32)*16 + ch*8);
            gemm_rowsN(acc, g_w + (size_t)(t+1)*NB + (warp*4)*64 + bg*4,
                       sW + (1024 + warp*4)*16 + ch*8, 4);
            if (warp == 15)
                gemm_rowsN(acc, g_xT + (size_t)(t+1)*192 + bg*4,
                           sW + 1088*16 + ch*8, 3);
        }
        if (tid == 0) bar_wait_ge(slot, (unsigned)(t+1) * NCTA);
        __syncthreads();
    }
}

// =========================================================================
// Output GEMM: out[b][t][o] = [h0,h1,h2][t] @ Wo + bo   (grid = 800 CTAs)
// =========================================================================
__global__ void __launch_bounds__(256)
k_out(const float* __restrict__ Wo, const float* __restrict__ bo,
      float* __restrict__ out)
{
    const int t = blockIdx.x;
    const int tid = threadIdx.x;
    const int c = tid & 127;
    const int bh = tid >> 7;
    if (c >= On) return;

    ull acc[16];
    ull bias2 = dup2(bo[c]);
    #pragma unroll
    for (int i = 0; i < 16; ++i) acc[i] = bias2;

    #pragma unroll
    for (int l = 0; l < 3; ++l) {
        const float* hp = (l == 0 ? g_h0 : l == 1 ? g_h1 : g_h2) + (size_t)t*HB;
        const float* wp = Wo + (l*512)*On + c;
        #pragma unroll 2
        for (int d = 0; d < 512; ++d) {
            ull wv = dup2(wp[d*On]);
            const ulonglong2* h4 = reinterpret_cast<const ulonglong2*>(hp + d*64 + bh*32);
            #pragma unroll
            for (int q = 0; q < 8; ++q) {
                ulonglong2 hv = h4[q];
                fma2(acc[2*q],   hv.x, wv);
                fma2(acc[2*q+1], hv.y, wv);
            }
        }
    }
    #pragma unroll
    for (int i = 0; i < 16; ++i) {
        float lo, hi; unpack2(acc[i], lo, hi);
        int b = bh*32 + 2*i;
        out[(size_t)b     *(Tn*On) + t*On + c] = lo;
        out[(size_t)(b+1) *(Tn*On) + t*On + c] = hi;
    }
}

// =========================================================================
extern "C" void kernel_launch(void* const* d_in, const int* in_sizes, int n_in,
                              void* d_out, int out_size)
{
    const float* strokes = (const float*)d_in[0];
    const float* trans   = (const float*)d_in[1];
    const float* W0      = (const float*)d_in[2];
    const float* R0      = (const float*)d_in[3];
    const float* b0      = (const float*)d_in[4];
    const float* Wd      = (const float*)d_in[5];
    const float* bd      = (const float*)d_in[6];
    const float* W1      = (const float*)d_in[7];
    const float* R1      = (const float*)d_in[8];
    const float* b1      = (const float*)d_in[9];
    const float* W2      = (const float*)d_in[10];
    const float* R2      = (const float*)d_in[11];
    const float* b2      = (const float*)d_in[12];
    const float* Wo      = (const float*)d_in[13];
    const float* bo      = (const float*)d_in[14];

    float* out = (float*)d_out;
    float* att = out + (size_t)Bn * Tn * On;

    const int smem_s2 = (17456 + 16384) * 4;   // 135360
    cudaFuncSetAttribute(k_scan01, cudaFuncAttributeMaxDynamicSharedMemorySize, SMEM_A);
    cudaFuncSetAttribute(k_scan2,  cudaFuncAttributeMaxDynamicSharedMemorySize, smem_s2);

    k_init<<<256, 256>>>(strokes);
    k_scan01<<<NGEMM + NATT, 512, SMEM_A>>>(trans, W0, R0, b0, Wd, bd,
                                            W1, R1, b1, att);
    k_scan2<<<NCTA, 512, smem_s2>>>(R2, W2, b2);
    k_out<<<Tn, 256>>>(Wo, bo, out);
}